// round 4
// baseline (speedup 1.0000x reference)
#include <cuda_runtime.h>
#include <math.h>

#define MAXN 50000
#define MAXE 800000
#define EB 64

// Scratch (static device arrays; no allocation).
__device__ __align__(16) float g_f[MAXN * 160];    // lin1 output per node: [f_s(64) | f_v(32x3)]
__device__ __align__(16) float g_sc[MAXN * 160];   // sc   output per node: [sc_s(64)| sc_v(32x3)]
__device__ __align__(16) float g_mid[MAXN * 384];  // segment-summed edge features

// ---------------------------------------------------------------------------
// Kernel A: node prep. 4 nodes per block, 160 threads.
// f_s = xs@lin1_w0 /8 * attr ; f_v = einsum(xv,lin1_w1)/sqrt32 * attr ; same for sc.
// Also zeroes g_mid rows.
// ---------------------------------------------------------------------------
__global__ void __launch_bounds__(160) node_prep(
    const float* __restrict__ ni, const float* __restrict__ attr,
    const float* __restrict__ scw0, const float* __restrict__ scw1,
    const float* __restrict__ l1w0, const float* __restrict__ l1w1, int N)
{
    int n0 = blockIdx.x * 4;
    int t = threadIdx.x;
    __shared__ float sx[4][160];

    #pragma unroll
    for (int q = 0; q < 4; q++) {
        int n = n0 + q;
        sx[q][t] = (n < N) ? ni[n * 160 + t] : 0.f;
    }
    #pragma unroll
    for (int q = 0; q < 4; q++) {
        int n = n0 + q;
        if (n < N)
            for (int i = t; i < 384; i += 160) g_mid[n * 384 + i] = 0.f;
    }
    __syncthreads();

    float aF[4], aS[4];
    if (t < 64) {
        float f0=0,f1=0,f2=0,f3=0, s0=0,s1=0,s2=0,s3=0;
        for (int i = 0; i < 64; i++) {
            float wf = l1w0[i * 64 + t], ws = scw0[i * 64 + t];
            float x0 = sx[0][i], x1 = sx[1][i], x2 = sx[2][i], x3 = sx[3][i];
            f0 += x0 * wf; f1 += x1 * wf; f2 += x2 * wf; f3 += x3 * wf;
            s0 += x0 * ws; s1 += x1 * ws; s2 += x2 * ws; s3 += x3 * ws;
        }
        const float sc = 0.125f;  // 1/sqrt(64)
        aF[0]=f0*sc; aF[1]=f1*sc; aF[2]=f2*sc; aF[3]=f3*sc;
        aS[0]=s0*sc; aS[1]=s1*sc; aS[2]=s2*sc; aS[3]=s3*sc;
    } else {
        int m = t - 64, w = m / 3, d = m - 3 * w;
        float f0=0,f1=0,f2=0,f3=0, s0=0,s1=0,s2=0,s3=0;
        for (int u = 0; u < 32; u++) {
            float wf = l1w1[u * 32 + w], ws = scw1[u * 32 + w];
            float x0 = sx[0][64 + 3*u + d], x1 = sx[1][64 + 3*u + d];
            float x2 = sx[2][64 + 3*u + d], x3 = sx[3][64 + 3*u + d];
            f0 += x0 * wf; f1 += x1 * wf; f2 += x2 * wf; f3 += x3 * wf;
            s0 += x0 * ws; s1 += x1 * ws; s2 += x2 * ws; s3 += x3 * ws;
        }
        const float sc = 0.17677669529663687f;  // 1/sqrt(32)
        aF[0]=f0*sc; aF[1]=f1*sc; aF[2]=f2*sc; aF[3]=f3*sc;
        aS[0]=s0*sc; aS[1]=s1*sc; aS[2]=s2*sc; aS[3]=s3*sc;
    }
    #pragma unroll
    for (int q = 0; q < 4; q++) {
        int n = n0 + q;
        if (n < N) {
            float a = attr[n];
            g_f[n * 160 + t]  = aF[q] * a;
            g_sc[n * 160 + t] = aS[q] * a;
        }
    }
}

// ---------------------------------------------------------------------------
// Kernel C: edge kernel. 64 edges per 256-thread block.
// h = silu(es@fc_w1/sqrt8)*0.125 (folds weight's 1/8); weight[j]=h@fc_w2[:,j],
// fused directly into feature atomics on g_mid[dst].
// ---------------------------------------------------------------------------
__global__ void __launch_bounds__(256, 2) edge_kernel(
    const float* __restrict__ eattr, const float* __restrict__ escal,
    const float* __restrict__ fw1, const float* __restrict__ fw2,
    const int* __restrict__ esrc, const int* __restrict__ edst, int E)
{
    extern __shared__ float smem[];
    float* sw2 = smem;                  // 64*192 = 12288
    float* sh  = sw2 + 12288;           // 64*64  =  4096
    float* sf  = sh + 4096;             // 64*160 = 10240
    float* sy  = sf + 10240;            // 64*4   =   256
    float* sw1 = sy + 256;              // 8*64   =   512
    float* ses = sw1 + 512;             // 64*8   =   512
    int*   sdst = (int*)(ses + 512);    // 64
    int*   ssrc = sdst + 64;            // 64

    int t = threadIdx.x;
    int e0 = blockIdx.x * EB;

    // ---- stage weights / edge inputs ----
    for (int i = t; i < 512; i += 256) sw1[i] = fw1[i];
    {
        const float4* s4 = (const float4*)fw2;
        float4* d4 = (float4*)sw2;
        for (int i = t; i < 3072; i += 256) d4[i] = s4[i];
    }
    if (t < 64) {
        int e = e0 + t;
        if (e < E) { sdst[t] = edst[e]; ssrc[t] = esrc[e]; }
        else       { sdst[t] = 0;       ssrc[t] = 0; }
    }
    {   // edge_attr: 64*4
        int e = e0 + (t >> 2);
        sy[t] = (e < E) ? eattr[e0 * 4 + t] : 0.f;
    }
    {   // edge_scalars: 64*8
        for (int i = t; i < 512; i += 256) {
            int e = e0 + (i >> 3);
            ses[i] = (e < E) ? escal[e0 * 8 + i] : 0.f;
        }
    }
    __syncthreads();

    // ---- gather f rows for the 64 edges (float4) ----
    {
        const float4* gf4 = (const float4*)g_f;
        float4* sf4 = (float4*)sf;
        for (int i = t; i < 2560; i += 256) {
            int e = i / 40, c = i - e * 40;
            sf4[e * 40 + c] = gf4[(size_t)ssrc[e] * 40 + c];
        }
    }

    // ---- phase 1: h = silu(es @ fc_w1 / sqrt8) * 0.125 ----
    {
        int kk = t & 63, eg = t >> 6;
        const float inv_s8 = 0.35355339059327373f;
        #pragma unroll
        for (int r = 0; r < 16; r++) {
            int e = eg + 4 * r;
            float acc = 0.f;
            #pragma unroll
            for (int i = 0; i < 8; i++) acc += ses[e * 8 + i] * sw1[i * 64 + kk];
            acc *= inv_s8;
            float sg = 1.f / (1.f + __expf(-acc));
            sh[e * 64 + kk] = 0.125f * acc * sg;
        }
    }
    __syncthreads();

    // ---- phase 2: weight GEMM (8 edges x 6 j-slices per thread) ----
    int lane = t & 31, grp = t >> 5;
    float acc[8][6];
    #pragma unroll
    for (int r = 0; r < 8; r++)
        #pragma unroll
        for (int m = 0; m < 6; m++) acc[r][m] = 0.f;

    const float* hp = sh + grp * 8 * 64;
    #pragma unroll 4
    for (int k = 0; k < 64; k++) {
        const float* wr = sw2 + k * 192 + lane;
        float w0 = wr[0],  w1 = wr[32],  w2 = wr[64];
        float w3 = wr[96], w4 = wr[128], w5 = wr[160];
        #pragma unroll
        for (int r = 0; r < 8; r++) {
            float hv = hp[r * 64 + k];
            acc[r][0] += hv * w0; acc[r][1] += hv * w1; acc[r][2] += hv * w2;
            acc[r][3] += hv * w3; acc[r][4] += hv * w4; acc[r][5] += hv * w5;
        }
    }

    // ---- epilogue: features + scatter-add ----
    const float INV3 = 0.5773502691896258f;
    #pragma unroll
    for (int r = 0; r < 8; r++) {
        int e = grp * 8 + r;
        if (e0 + e >= E) continue;
        float ys = sy[e * 4 + 0], y0 = sy[e * 4 + 1];
        float y1 = sy[e * 4 + 2], y2 = sy[e * 4 + 3];
        const float* fe = sf + e * 160;
        float gsa = fe[lane], gsb = fe[lane + 32];
        float gv0 = fe[64 + 3*lane], gv1 = fe[65 + 3*lane], gv2 = fe[66 + 3*lane];
        float* mb = g_mid + (size_t)sdst[e] * 384;

        atomicAdd(mb + lane,      gsa * ys * acc[r][0]);        // m0a j
        atomicAdd(mb + 32 + lane, gsb * ys * acc[r][1]);        // m0a j+32
        float wa = acc[r][2];                                   // m1a u=lane
        atomicAdd(mb + 96  + 3*lane, gsa * y0 * wa);
        atomicAdd(mb + 97  + 3*lane, gsa * y1 * wa);
        atomicAdd(mb + 98  + 3*lane, gsa * y2 * wa);
        float wb = acc[r][3];                                   // m1a u=lane+32
        atomicAdd(mb + 192 + 3*lane, gsb * y0 * wb);
        atomicAdd(mb + 193 + 3*lane, gsb * y1 * wb);
        atomicAdd(mb + 194 + 3*lane, gsb * y2 * wb);
        float wc = acc[r][4];                                   // m1b u=lane
        atomicAdd(mb + 288 + 3*lane, gv0 * ys * wc);
        atomicAdd(mb + 289 + 3*lane, gv1 * ys * wc);
        atomicAdd(mb + 290 + 3*lane, gv2 * ys * wc);
        float wd = acc[r][5];                                   // m0b u=lane
        atomicAdd(mb + 64 + lane, (gv0*y0 + gv1*y1 + gv2*y2) * INV3 * wd);
    }
}

// ---------------------------------------------------------------------------
// Kernel D: node post. 4 nodes per block, 160 threads.
// mid /= sqrt(nn); lin2 FCTP; angle; out = cos(a)*scfeat + sin(a)*conv.
// ---------------------------------------------------------------------------
__global__ void __launch_bounds__(160) node_final(
    const float* __restrict__ attr, const float* __restrict__ l2w0,
    const float* __restrict__ l2w1, const float* __restrict__ l3w,
    const int* __restrict__ nnb, float* __restrict__ out, int N)
{
    int n0 = blockIdx.x * 4;
    int t = threadIdx.x;
    __shared__ float sm[4][384];
    __shared__ float sang[4];
    float scale = rsqrtf((float)nnb[0]);

    #pragma unroll
    for (int q = 0; q < 4; q++) {
        int n = n0 + q;
        for (int i = t; i < 384; i += 160)
            sm[q][i] = (n < N) ? g_mid[n * 384 + i] * scale : 0.f;
    }
    __syncthreads();

    const float inv96 = 0.10206207261596575f;  // 1/sqrt(96)
    if (t < 32) {
        #pragma unroll
        for (int q = 0; q < 4; q++) {
            float s = 0.f;
            for (int i = t; i < 96; i += 32) s += sm[q][i] * l3w[i];
            #pragma unroll
            for (int o = 16; o; o >>= 1) s += __shfl_xor_sync(0xffffffffu, s, o);
            if (t == 0) {
                int n = n0 + q;
                sang[q] = (n < N) ? 0.1f * s * inv96 * attr[n] : 0.f;
            }
        }
    }

    float c[4];
    if (t < 64) {
        float a0=0,a1=0,a2=0,a3=0;
        for (int i = 0; i < 96; i++) {
            float w = l2w0[i * 64 + t];
            a0 += sm[0][i]*w; a1 += sm[1][i]*w; a2 += sm[2][i]*w; a3 += sm[3][i]*w;
        }
        c[0]=a0*inv96; c[1]=a1*inv96; c[2]=a2*inv96; c[3]=a3*inv96;
    } else {
        int m = t - 64, w = m / 3, d = m - 3 * w;
        float a0=0,a1=0,a2=0,a3=0;
        for (int u = 0; u < 96; u++) {
            float ww = l2w1[u * 32 + w];
            int idx = 96 + 3*u + d;
            a0 += sm[0][idx]*ww; a1 += sm[1][idx]*ww; a2 += sm[2][idx]*ww; a3 += sm[3][idx]*ww;
        }
        c[0]=a0*inv96; c[1]=a1*inv96; c[2]=a2*inv96; c[3]=a3*inv96;
    }
    __syncthreads();

    #pragma unroll
    for (int q = 0; q < 4; q++) {
        int n = n0 + q;
        if (n >= N) continue;
        float a = attr[n];
        float sn, cs;
        __sincosf(sang[q], &sn, &cs);
        out[n * 160 + t] = cs * g_sc[n * 160 + t] + sn * c[q] * a;
    }
}

// ---------------------------------------------------------------------------
extern "C" void kernel_launch(void* const* d_in, const int* in_sizes, int n_in,
                              void* d_out, int out_size)
{
    const float* node_input   = (const float*)d_in[0];
    const float* node_attr    = (const float*)d_in[1];
    const float* edge_attr    = (const float*)d_in[2];
    const float* edge_scalars = (const float*)d_in[3];
    const float* sc_w0        = (const float*)d_in[4];
    const float* sc_w1        = (const float*)d_in[5];
    const float* lin1_w0      = (const float*)d_in[6];
    const float* lin1_w1      = (const float*)d_in[7];
    const float* fc_w1        = (const float*)d_in[8];
    const float* fc_w2        = (const float*)d_in[9];
    const float* lin2_w0      = (const float*)d_in[10];
    const float* lin2_w1      = (const float*)d_in[11];
    const float* lin3_w       = (const float*)d_in[12];
    const int*   edge_src     = (const int*)d_in[13];
    const int*   edge_dst     = (const int*)d_in[14];
    const int*   num_neigh    = (const int*)d_in[15];

    int N = in_sizes[1];   // node_attr is (N,1)
    int E = in_sizes[13];  // edge_src is (E,)
    float* out = (float*)d_out;

    const int smem_bytes = 28032 * 4;  // 112128 B dynamic smem for edge kernel
    cudaFuncSetAttribute(edge_kernel, cudaFuncAttributeMaxDynamicSharedMemorySize,
                         smem_bytes);

    node_prep<<<(N + 3) / 4, 160>>>(node_input, node_attr, sc_w0, sc_w1,
                                    lin1_w0, lin1_w1, N);
    edge_kernel<<<(E + EB - 1) / EB, 256, smem_bytes>>>(
        edge_attr, edge_scalars, fc_w1, fc_w2, edge_src, edge_dst, E);
    node_final<<<(N + 3) / 4, 160>>>(node_attr, lin2_w0, lin2_w1, lin3_w,
                                     num_neigh, out, N);
}

// round 14
// speedup vs baseline: 1.0396x; 1.0396x over previous
#include <cuda_runtime.h>
#include <math.h>

#define MAXN 50000
#define MAXE 800000
#define EB 64

// Scratch (static device arrays; no allocation).
__device__ __align__(16) float g_f[MAXN * 160];    // lin1 output per node: [f_s(64) | f_v(32x3)]
__device__ __align__(16) float g_sc[MAXN * 160];   // sc   output per node: [sc_s(64)| sc_v(32x3)]
// g_mid: PERMUTED layout. Node n, lane l (0..31) owns floats [n*384 + l*12 .. +11]:
//   slot 0: m0a(j=l)        slot 1: m0a(j=l+32)   slot 2: m0b(u=l)
//   slot 3..5:  m1a(u=l,    d=0..2)
//   slot 6..8:  m1a(u=l+32, d=0..2)
//   slot 9..11: m1b(u=l,    d=0..2)
__device__ __align__(16) float g_mid[MAXN * 384];

// logical->physical index maps for the permuted g_mid layout
__device__ __forceinline__ int phys_s(int j) {            // scalar part, j in 0..95
    return (j & 31) * 12 + (j >> 5);
}
__device__ __forceinline__ int phys_v(int u, int d) {     // vector part, u in 0..95
    return (u & 31) * 12 + 3 + 3 * (u >> 5) + d;
}

// vectorized float4 reduction (sm_90+): one L2 atomic op for 16 bytes
__device__ __forceinline__ void red4(float* p, float a, float b, float c, float d) {
    asm volatile("red.global.add.v4.f32 [%0], {%1,%2,%3,%4};"
                 :: "l"(p), "f"(a), "f"(b), "f"(c), "f"(d) : "memory");
}

// ---------------------------------------------------------------------------
// Kernel A: node prep. 4 nodes per block, 160 threads.
// ---------------------------------------------------------------------------
__global__ void __launch_bounds__(160) node_prep(
    const float* __restrict__ ni, const float* __restrict__ attr,
    const float* __restrict__ scw0, const float* __restrict__ scw1,
    const float* __restrict__ l1w0, const float* __restrict__ l1w1, int N)
{
    int n0 = blockIdx.x * 4;
    int t = threadIdx.x;
    __shared__ float sx[4][160];

    #pragma unroll
    for (int q = 0; q < 4; q++) {
        int n = n0 + q;
        sx[q][t] = (n < N) ? ni[n * 160 + t] : 0.f;
    }
    #pragma unroll
    for (int q = 0; q < 4; q++) {
        int n = n0 + q;
        if (n < N)
            for (int i = t; i < 384; i += 160) g_mid[n * 384 + i] = 0.f;
    }
    __syncthreads();

    float aF[4], aS[4];
    if (t < 64) {
        float f0=0,f1=0,f2=0,f3=0, s0=0,s1=0,s2=0,s3=0;
        for (int i = 0; i < 64; i++) {
            float wf = l1w0[i * 64 + t], ws = scw0[i * 64 + t];
            float x0 = sx[0][i], x1 = sx[1][i], x2 = sx[2][i], x3 = sx[3][i];
            f0 += x0 * wf; f1 += x1 * wf; f2 += x2 * wf; f3 += x3 * wf;
            s0 += x0 * ws; s1 += x1 * ws; s2 += x2 * ws; s3 += x3 * ws;
        }
        const float sc = 0.125f;  // 1/sqrt(64)
        aF[0]=f0*sc; aF[1]=f1*sc; aF[2]=f2*sc; aF[3]=f3*sc;
        aS[0]=s0*sc; aS[1]=s1*sc; aS[2]=s2*sc; aS[3]=s3*sc;
    } else {
        int m = t - 64, w = m / 3, d = m - 3 * w;
        float f0=0,f1=0,f2=0,f3=0, s0=0,s1=0,s2=0,s3=0;
        for (int u = 0; u < 32; u++) {
            float wf = l1w1[u * 32 + w], ws = scw1[u * 32 + w];
            float x0 = sx[0][64 + 3*u + d], x1 = sx[1][64 + 3*u + d];
            float x2 = sx[2][64 + 3*u + d], x3 = sx[3][64 + 3*u + d];
            f0 += x0 * wf; f1 += x1 * wf; f2 += x2 * wf; f3 += x3 * wf;
            s0 += x0 * ws; s1 += x1 * ws; s2 += x2 * ws; s3 += x3 * ws;
        }
        const float sc = 0.17677669529663687f;  // 1/sqrt(32)
        aF[0]=f0*sc; aF[1]=f1*sc; aF[2]=f2*sc; aF[3]=f3*sc;
        aS[0]=s0*sc; aS[1]=s1*sc; aS[2]=s2*sc; aS[3]=s3*sc;
    }
    #pragma unroll
    for (int q = 0; q < 4; q++) {
        int n = n0 + q;
        if (n < N) {
            float a = attr[n];
            g_f[n * 160 + t]  = aF[q] * a;
            g_sc[n * 160 + t] = aS[q] * a;
        }
    }
}

// ---------------------------------------------------------------------------
// Kernel C: edge kernel. 64 edges per 256-thread block.
// Epilogue uses 3 x red.global.add.v4.f32 per lane per edge (permuted g_mid).
// ---------------------------------------------------------------------------
__global__ void __launch_bounds__(256, 2) edge_kernel(
    const float* __restrict__ eattr, const float* __restrict__ escal,
    const float* __restrict__ fw1, const float* __restrict__ fw2,
    const int* __restrict__ esrc, const int* __restrict__ edst, int E)
{
    extern __shared__ float smem[];
    float* sw2 = smem;                  // 64*192 = 12288
    float* sh  = sw2 + 12288;           // 64*64  =  4096
    float* sf  = sh + 4096;             // 64*160 = 10240
    float* sy  = sf + 10240;            // 64*4   =   256
    float* sw1 = sy + 256;              // 8*64   =   512
    float* ses = sw1 + 512;             // 64*8   =   512
    int*   sdst = (int*)(ses + 512);    // 64
    int*   ssrc = sdst + 64;            // 64

    int t = threadIdx.x;
    int e0 = blockIdx.x * EB;

    // ---- stage weights / edge inputs ----
    for (int i = t; i < 512; i += 256) sw1[i] = fw1[i];
    {
        const float4* s4 = (const float4*)fw2;
        float4* d4 = (float4*)sw2;
        for (int i = t; i < 3072; i += 256) d4[i] = s4[i];
    }
    if (t < 64) {
        int e = e0 + t;
        if (e < E) { sdst[t] = edst[e]; ssrc[t] = esrc[e]; }
        else       { sdst[t] = 0;       ssrc[t] = 0; }
    }
    {   // edge_attr: 64*4
        int e = e0 + (t >> 2);
        sy[t] = (e < E) ? eattr[e0 * 4 + t] : 0.f;
    }
    {   // edge_scalars: 64*8
        for (int i = t; i < 512; i += 256) {
            int e = e0 + (i >> 3);
            ses[i] = (e < E) ? escal[e0 * 8 + i] : 0.f;
        }
    }
    __syncthreads();

    // ---- gather f rows for the 64 edges (float4) ----
    {
        const float4* gf4 = (const float4*)g_f;
        float4* sf4 = (float4*)sf;
        for (int i = t; i < 2560; i += 256) {
            int e = i / 40, c = i - e * 40;
            sf4[e * 40 + c] = gf4[(size_t)ssrc[e] * 40 + c];
        }
    }

    // ---- phase 1: h = silu(es @ fc_w1 / sqrt8) * 0.125 ----
    {
        int kk = t & 63, eg = t >> 6;
        const float inv_s8 = 0.35355339059327373f;
        #pragma unroll
        for (int r = 0; r < 16; r++) {
            int e = eg + 4 * r;
            float acc = 0.f;
            #pragma unroll
            for (int i = 0; i < 8; i++) acc += ses[e * 8 + i] * sw1[i * 64 + kk];
            acc *= inv_s8;
            float sg = 1.f / (1.f + __expf(-acc));
            sh[e * 64 + kk] = 0.125f * acc * sg;
        }
    }
    __syncthreads();

    // ---- phase 2: weight GEMM (8 edges x 6 j-slices per thread) ----
    int lane = t & 31, grp = t >> 5;
    float acc[8][6];
    #pragma unroll
    for (int r = 0; r < 8; r++)
        #pragma unroll
        for (int m = 0; m < 6; m++) acc[r][m] = 0.f;

    const float* hp = sh + grp * 8 * 64;
    #pragma unroll 4
    for (int k = 0; k < 64; k++) {
        const float* wr = sw2 + k * 192 + lane;
        float w0 = wr[0],  w1 = wr[32],  w2 = wr[64];
        float w3 = wr[96], w4 = wr[128], w5 = wr[160];
        #pragma unroll
        for (int r = 0; r < 8; r++) {
            float hv = hp[r * 64 + k];
            acc[r][0] += hv * w0; acc[r][1] += hv * w1; acc[r][2] += hv * w2;
            acc[r][3] += hv * w3; acc[r][4] += hv * w4; acc[r][5] += hv * w5;
        }
    }

    // ---- epilogue: features + vectorized scatter-add ----
    const float INV3 = 0.5773502691896258f;
    #pragma unroll
    for (int r = 0; r < 8; r++) {
        int e = grp * 8 + r;
        if (e0 + e >= E) continue;
        float ys = sy[e * 4 + 0], y0 = sy[e * 4 + 1];
        float y1 = sy[e * 4 + 2], y2 = sy[e * 4 + 3];
        const float* fe = sf + e * 160;
        float gsa = fe[lane], gsb = fe[lane + 32];
        float gv0 = fe[64 + 3*lane], gv1 = fe[65 + 3*lane], gv2 = fe[66 + 3*lane];
        float* mb = g_mid + (size_t)sdst[e] * 384 + lane * 12;

        float wa = acc[r][2], wb = acc[r][3], wc = acc[r][4];
        float s0 = gsa * ys * acc[r][0];                         // m0a(l)
        float s1 = gsb * ys * acc[r][1];                         // m0a(l+32)
        float s2 = (gv0*y0 + gv1*y1 + gv2*y2) * INV3 * acc[r][5];// m0b(l)

        red4(mb,     s0,         s1,         s2,         gsa * y0 * wa);
        red4(mb + 4, gsa*y1*wa,  gsa*y2*wa,  gsb*y0*wb,  gsb * y1 * wb);
        red4(mb + 8, gsb*y2*wb,  gv0*ys*wc,  gv1*ys*wc,  gv2 * ys * wc);
    }
}

// ---------------------------------------------------------------------------
// Kernel D: node post. 4 nodes per block, 160 threads. Un-permutes g_mid.
// ---------------------------------------------------------------------------
__global__ void __launch_bounds__(160) node_final(
    const float* __restrict__ attr, const float* __restrict__ l2w0,
    const float* __restrict__ l2w1, const float* __restrict__ l3w,
    const int* __restrict__ nnb, float* __restrict__ out, int N)
{
    int n0 = blockIdx.x * 4;
    int t = threadIdx.x;
    __shared__ float sm[4][384];    // physical (permuted) layout
    __shared__ float sang[4];
    float scale = rsqrtf((float)nnb[0]);

    #pragma unroll
    for (int q = 0; q < 4; q++) {
        int n = n0 + q;
        for (int i = t; i < 384; i += 160)
            sm[q][i] = (n < N) ? g_mid[n * 384 + i] * scale : 0.f;
    }
    __syncthreads();

    const float inv96 = 0.10206207261596575f;  // 1/sqrt(96)
    if (t < 32) {
        #pragma unroll
        for (int q = 0; q < 4; q++) {
            float s = 0.f;
            #pragma unroll
            for (int i = 0; i < 3; i++) s += sm[q][phys_s(t + 32 * i)] * l3w[t + 32 * i];
            #pragma unroll
            for (int o = 16; o; o >>= 1) s += __shfl_xor_sync(0xffffffffu, s, o);
            if (t == 0) {
                int n = n0 + q;
                sang[q] = (n < N) ? 0.1f * s * inv96 * attr[n] : 0.f;
            }
        }
    }

    float c[4];
    if (t < 64) {
        float a0=0,a1=0,a2=0,a3=0;
        for (int i = 0; i < 96; i++) {
            float w = l2w0[i * 64 + t];
            int p = phys_s(i);
            a0 += sm[0][p]*w; a1 += sm[1][p]*w; a2 += sm[2][p]*w; a3 += sm[3][p]*w;
        }
        c[0]=a0*inv96; c[1]=a1*inv96; c[2]=a2*inv96; c[3]=a3*inv96;
    } else {
        int m = t - 64, w = m / 3, d = m - 3 * w;
        float a0=0,a1=0,a2=0,a3=0;
        for (int u = 0; u < 96; u++) {
            float ww = l2w1[u * 32 + w];
            int p = phys_v(u, d);
            a0 += sm[0][p]*ww; a1 += sm[1][p]*ww; a2 += sm[2][p]*ww; a3 += sm[3][p]*ww;
        }
        c[0]=a0*inv96; c[1]=a1*inv96; c[2]=a2*inv96; c[3]=a3*inv96;
    }
    __syncthreads();

    #pragma unroll
    for (int q = 0; q < 4; q++) {
        int n = n0 + q;
        if (n >= N) continue;
        float a = attr[n];
        float sn, cs;
        __sincosf(sang[q], &sn, &cs);
        out[n * 160 + t] = cs * g_sc[n * 160 + t] + sn * c[q] * a;
    }
}

// ---------------------------------------------------------------------------
extern "C" void kernel_launch(void* const* d_in, const int* in_sizes, int n_in,
                              void* d_out, int out_size)
{
    const float* node_input   = (const float*)d_in[0];
    const float* node_attr    = (const float*)d_in[1];
    const float* edge_attr    = (const float*)d_in[2];
    const float* edge_scalars = (const float*)d_in[3];
    const float* sc_w0        = (const float*)d_in[4];
    const float* sc_w1        = (const float*)d_in[5];
    const float* lin1_w0      = (const float*)d_in[6];
    const float* lin1_w1      = (const float*)d_in[7];
    const float* fc_w1        = (const float*)d_in[8];
    const float* fc_w2        = (const float*)d_in[9];
    const float* lin2_w0      = (const float*)d_in[10];
    const float* lin2_w1      = (const float*)d_in[11];
    const float* lin3_w       = (const float*)d_in[12];
    const int*   edge_src     = (const int*)d_in[13];
    const int*   edge_dst     = (const int*)d_in[14];
    const int*   num_neigh    = (const int*)d_in[15];

    int N = in_sizes[1];   // node_attr is (N,1)
    int E = in_sizes[13];  // edge_src is (E,)
    float* out = (float*)d_out;

    const int smem_bytes = 28032 * 4;  // 112128 B dynamic smem for edge kernel
    cudaFuncSetAttribute(edge_kernel, cudaFuncAttributeMaxDynamicSharedMemorySize,
                         smem_bytes);

    node_prep<<<(N + 3) / 4, 160>>>(node_input, node_attr, sc_w0, sc_w1,
                                    lin1_w0, lin1_w1, N);
    edge_kernel<<<(E + EB - 1) / EB, 256, smem_bytes>>>(
        edge_attr, edge_scalars, fc_w1, fc_w2, edge_src, edge_dst, E);
    node_final<<<(N + 3) / 4, 160>>>(node_attr, lin2_w0, lin2_w1, lin3_w,
                                     num_neigh, out, N);
}